// round 6
// baseline (speedup 1.0000x reference)
#include <cuda_runtime.h>

#define N_NODES 50000
#define N_EDGES 800000
#define NPAD    50048     // node stride (mult of 64, 128B rows)
#define IN_C  64
#define HID_C 128
#define OUT_C 40
#define CAP   96

// ---------------- scratch (zero-initialized; pad columns stay 0 forever) ---
__device__ float g_u1T[IN_C  * NPAD];   // (1+eps1)*x+agg, transposed [c][n]
__device__ float g_h1T[HID_C * NPAD];   // relu(u1@w1a+b1a), transposed
__device__ float g_hrel[N_NODES * HID_C]; // node-major (for gather)
__device__ float g_u2T[HID_C * NPAD];   // transposed
__device__ float g_tT [HID_C * NPAD];   // relu(u2@w2a+b2a), transposed
__device__ int   g_deg[N_NODES];
__device__ int   g_bucket[N_NODES * CAP];
__device__ int   g_ei_is64;

// ---------------- packed f32x2 helpers ----------------
typedef unsigned long long ull;
__device__ __forceinline__ ull fma2(ull a, ull b, ull c) {
    ull d;
    asm("fma.rn.f32x2 %0, %1, %2, %3;" : "=l"(d) : "l"(a), "l"(b), "l"(c));
    return d;
}
__device__ __forceinline__ ull pack2(float x) {
    ull d;
    asm("mov.b64 %0, {%1, %1};" : "=l"(d) : "f"(x));
    return d;
}
__device__ __forceinline__ void unpack2(ull v, float& lo, float& hi) {
    asm("mov.b64 {%0, %1}, %2;" : "=f"(lo), "=f"(hi) : "l"(v));
}
union F4U2 { float4 f; ull u[2]; };

// ---------------- dtype detection ----------------
__global__ void detect_ei_kernel(const unsigned int* __restrict__ w) {
    int ok = (w[2 * threadIdx.x + 1] == 0u) ? 1 : 0;
    int all = __syncthreads_and(ok);
    if (threadIdx.x == 0) g_ei_is64 = all;
}

// ---------------- bucket fill ----------------
__global__ void __launch_bounds__(256) fill_kernel(const void* __restrict__ eiv) {
    int e = blockIdx.x * 256 + threadIdx.x;
    int s, d;
    if (g_ei_is64) {
        const long long* ei = (const long long*)eiv;
        s = (int)ei[e]; d = (int)ei[N_EDGES + e];
    } else {
        const int* ei = (const int*)eiv;
        s = ei[e]; d = ei[N_EDGES + e];
    }
    if ((unsigned)s >= N_NODES || (unsigned)d >= N_NODES) return;
    int pos = atomicAdd(&g_deg[d], 1);
    if (pos < CAP) g_bucket[d * CAP + pos] = s;
}

// ---------------- agg1: u1T[c][n] = (1+eps1)*x[n][c] + sum_nbr x[s][c] -----
// 256 thr, 64 nodes/block; warp handles 8 nodes; smem transpose then
// coalesced transposed global write.
__global__ void __launch_bounds__(256) agg1_kernel(
    const float* __restrict__ x, const float* __restrict__ eps1p,
    float* __restrict__ u1T)
{
    __shared__ float sm[64 * 66];
    const int tid = threadIdx.x, lane = tid & 31, wid = tid >> 5;
    const int n0 = blockIdx.x * 64;
    const float ep = 1.0f + *eps1p;

    for (int k = 0; k < 8; k++) {
        int nl = wid * 8 + k;
        int n = n0 + nl;
        float2 acc = make_float2(0.f, 0.f);
        if (n < N_NODES) {
            int deg = g_deg[n]; if (deg > CAP) deg = CAP;
            const int* bkt = &g_bucket[n * CAP];
            for (int i = 0; i < deg; i++) {
                int s = bkt[i];
                float2 v = *reinterpret_cast<const float2*>(x + (size_t)s * IN_C + lane * 2);
                acc.x += v.x; acc.y += v.y;
            }
            float2 xv = *reinterpret_cast<const float2*>(x + (size_t)n * IN_C + lane * 2);
            acc.x = ep * xv.x + acc.x;
            acc.y = ep * xv.y + acc.y;
        }
        *reinterpret_cast<float2*>(&sm[nl * 66 + lane * 2]) = acc;
    }
    __syncthreads();
    // transposed write: rows c, 64 consecutive nodes
    for (int i = tid; i < 64 * IN_C; i += 256) {
        int n = i & 63, c = i >> 6;
        u1T[(size_t)c * NPAD + n0 + n] = sm[n * 66 + c];
    }
}

// ---------------- agg2: u2T[c][n] = (1+eps2)*h[n][c] + sum_nbr h[s][c] -----
__global__ void __launch_bounds__(256) agg2_kernel(
    const float* __restrict__ h, const float* __restrict__ eps2p,
    float* __restrict__ u2T)
{
    __shared__ float sm[64 * 132];
    const int tid = threadIdx.x, lane = tid & 31, wid = tid >> 5;
    const int n0 = blockIdx.x * 64;
    const float ep = 1.0f + *eps2p;

    for (int k = 0; k < 8; k++) {
        int nl = wid * 8 + k;
        int n = n0 + nl;
        float4 acc = make_float4(0.f, 0.f, 0.f, 0.f);
        if (n < N_NODES) {
            int deg = g_deg[n]; if (deg > CAP) deg = CAP;
            const int* bkt = &g_bucket[n * CAP];
            for (int i = 0; i < deg; i++) {
                int s = bkt[i];
                float4 v = *reinterpret_cast<const float4*>(h + (size_t)s * HID_C + lane * 4);
                acc.x += v.x; acc.y += v.y; acc.z += v.z; acc.w += v.w;
            }
            float4 hv = *reinterpret_cast<const float4*>(h + (size_t)n * HID_C + lane * 4);
            acc.x = ep * hv.x + acc.x; acc.y = ep * hv.y + acc.y;
            acc.z = ep * hv.z + acc.z; acc.w = ep * hv.w + acc.w;
        }
        *reinterpret_cast<float4*>(&sm[nl * 132 + lane * 4]) = acc;
    }
    __syncthreads();
    for (int i = tid; i < 64 * HID_C; i += 256) {
        int n = i & 63, c = i >> 6;
        u2T[(size_t)c * NPAD + n0 + n] = sm[n * 132 + c];
    }
}

// ================= packed GEMM: [K]x[n-tile] -> 128 outs =================
// 256 thr, 8 warps x 8 nodes = 64 nodes/block; thread: 4 node-pairs x 4 outs.
// TRANS_OUT: store to outT[j][n] (float2), else out[n][j] scalar, RELU always.
template<int K, int WPAD, bool TRANS_OUT>
__device__ __forceinline__ void gemm_body(
    const float* __restrict__ inT,   // [K][NPAD]
    const float* __restrict__ w,     // [K][128] row-major
    const float* __restrict__ b,     // [128]
    float* __restrict__ outp,        // outT [128][NPAD] or out [N][128]
    float* sm)                       // smem: w T [128][WPAD] + xT [K][68] + b[128]
{
    float* wT  = sm;                      // [128][WPAD]
    float* xT  = sm + 128 * WPAD;         // [K][68]
    float* bs  = xT + K * 68;             // [128]

    const int tid = threadIdx.x;
    const int n0 = blockIdx.x * 64;

    for (int i = tid; i < K * 128; i += 256) {
        int c = i >> 7, j = i & 127;
        wT[j * WPAD + c] = w[i];
    }
    if (tid < 128) bs[tid] = b[tid];
    for (int i = tid; i < K * 16; i += 256) {
        int c = i >> 4, q = i & 15;
        float4 v = *reinterpret_cast<const float4*>(&inT[(size_t)c * NPAD + n0 + 4 * q]);
        *reinterpret_cast<float4*>(&xT[c * 68 + 4 * q]) = v;
    }
    __syncthreads();

    const int tx = tid & 31;
    const int nb_local = (tid >> 5) * 8;

    ull acc[4][4];
    #pragma unroll
    for (int jj = 0; jj < 4; jj++) {
        ull bp = pack2(bs[tx + 32 * jj]);
        #pragma unroll
        for (int p = 0; p < 4; p++) acc[p][jj] = bp;
    }

    #pragma unroll 4
    for (int c4 = 0; c4 < K; c4 += 4) {
        float4 wv[4];
        #pragma unroll
        for (int jj = 0; jj < 4; jj++)
            wv[jj] = *reinterpret_cast<const float4*>(&wT[(tx + 32 * jj) * WPAD + c4]);
        #pragma unroll
        for (int cc = 0; cc < 4; cc++) {
            F4U2 x0, x1;
            x0.f = *reinterpret_cast<const float4*>(&xT[(c4 + cc) * 68 + nb_local]);
            x1.f = *reinterpret_cast<const float4*>(&xT[(c4 + cc) * 68 + nb_local + 4]);
            ull xp[4] = { x0.u[0], x0.u[1], x1.u[0], x1.u[1] };
            #pragma unroll
            for (int jj = 0; jj < 4; jj++) {
                float ws = (cc == 0) ? wv[jj].x : (cc == 1) ? wv[jj].y
                         : (cc == 2) ? wv[jj].z : wv[jj].w;
                ull wp = pack2(ws);
                #pragma unroll
                for (int p = 0; p < 4; p++)
                    acc[p][jj] = fma2(xp[p], wp, acc[p][jj]);
            }
        }
    }

    const int nb = n0 + nb_local;
    #pragma unroll
    for (int p = 0; p < 4; p++) {
        int n = nb + 2 * p;
        if (n >= N_NODES) continue;
        #pragma unroll
        for (int jj = 0; jj < 4; jj++) {
            float lo, hi;
            unpack2(acc[p][jj], lo, hi);
            lo = fmaxf(lo, 0.0f); hi = fmaxf(hi, 0.0f);
            int j = tx + 32 * jj;
            if (TRANS_OUT) {
                *reinterpret_cast<float2*>(&outp[(size_t)j * NPAD + n]) = make_float2(lo, hi);
            } else {
                outp[(size_t)n * HID_C + j] = lo;
                outp[(size_t)(n + 1) * HID_C + j] = hi;
            }
        }
    }
}

// k1a: u1T(64) -> h1T(128), relu, transposed out. smem: 128*68+64*68+128 fl
#define SMEM_K1A ((128 * 68 + 64 * 68 + 128) * 4)
__global__ void __launch_bounds__(256, 3) k1a_kernel(
    const float* __restrict__ u1T, const float* __restrict__ w1a,
    const float* __restrict__ b1a, float* __restrict__ h1T)
{
    extern __shared__ float sm[];
    gemm_body<64, 68, true>(u1T, w1a, b1a, h1T, sm);
}

// k1b: h1T(128) -> hrel(node-major 128), relu. smem: 128*132+128*68+128
#define SMEM_K1B ((128 * 132 + 128 * 68 + 128) * 4)
__global__ void __launch_bounds__(256, 2) k1b_kernel(
    const float* __restrict__ h1T, const float* __restrict__ w1b,
    const float* __restrict__ b1b, float* __restrict__ hrel)
{
    extern __shared__ float sm[];
    gemm_body<128, 132, false>(h1T, w1b, b1b, hrel, sm);
}

// k2a: u2T(128) -> tT(128), relu, transposed out
__global__ void __launch_bounds__(256, 2) k2a_kernel(
    const float* __restrict__ u2T, const float* __restrict__ w2a,
    const float* __restrict__ b2a, float* __restrict__ tT)
{
    extern __shared__ float sm[];
    gemm_body<128, 132, true>(u2T, w2a, b2a, tT, sm);
}

// ---------------- k2b: tT(128) -> 40 logits + log_softmax ----------------
// 256 thr, 64 nodes/block.
#define C_W2BT 0                        // [40][132]
#define C_TS   (40 * 132)               // [64][132]
#define C_OO   (C_TS + 64 * 132)        // [64][40]
#define C_B2B  (C_OO + 64 * 40)         // [40]
#define C_CORR (C_B2B + 64)             // [64]
#define SMEM_K2B ((C_CORR + 64) * 4)

__global__ void __launch_bounds__(256) k2b_kernel(
    const float* __restrict__ tT, const float* __restrict__ w2b,
    const float* __restrict__ b2b, float* __restrict__ out)
{
    extern __shared__ float sm[];
    float* w2bT = sm + C_W2BT;
    float* tS   = sm + C_TS;
    float* oout = sm + C_OO;
    float* b2bs = sm + C_B2B;
    float* corr = sm + C_CORR;

    const int tid = threadIdx.x;
    const int n0 = blockIdx.x * 64;

    for (int i = tid; i < HID_C * OUT_C; i += 256) {
        int c = i / OUT_C, j = i - c * OUT_C;
        w2bT[j * 132 + c] = w2b[i];
    }
    if (tid < OUT_C) b2bs[tid] = b2b[tid];
    // load tile transposed back to [n][c]
    for (int i = tid; i < HID_C * 16; i += 256) {
        int c = i >> 4, q = i & 15;
        float4 v = *reinterpret_cast<const float4*>(&tT[(size_t)c * NPAD + n0 + 4 * q]);
        tS[(4 * q + 0) * 132 + c] = v.x;
        tS[(4 * q + 1) * 132 + c] = v.y;
        tS[(4 * q + 2) * 132 + c] = v.z;
        tS[(4 * q + 3) * 132 + c] = v.w;
    }
    __syncthreads();

    for (int idx = tid; idx < 64 * OUT_C; idx += 256) {
        int n = idx / OUT_C;
        int j = idx - n * OUT_C;
        float a = b2bs[j];
        const float* wr = &w2bT[j * 132];
        const float* tr = &tS[n * 132];
        #pragma unroll
        for (int c = 0; c < HID_C; c += 4) {
            float4 wv = *reinterpret_cast<const float4*>(wr + c);
            float4 tv = *reinterpret_cast<const float4*>(tr + c);
            a += wv.x * tv.x + wv.y * tv.y + wv.z * tv.z + wv.w * tv.w;
        }
        oout[idx] = a;
    }
    __syncthreads();

    if (tid < 64) {
        const float* o = &oout[tid * OUT_C];
        float m = o[0];
        #pragma unroll
        for (int j = 1; j < OUT_C; j++) m = fmaxf(m, o[j]);
        float s = 0.0f;
        #pragma unroll
        for (int j = 0; j < OUT_C; j++) s += __expf(o[j] - m);
        corr[tid] = m + logf(s);
    }
    __syncthreads();

    for (int idx = tid; idx < 64 * OUT_C; idx += 256) {
        int n = idx / OUT_C;
        int g = n0 + n;
        if (g < N_NODES) out[(size_t)g * OUT_C + (idx - n * OUT_C)] = oout[idx] - corr[n];
    }
}

// ================= launch =================
extern "C" void kernel_launch(void* const* d_in, const int* in_sizes, int n_in,
                              void* d_out, int out_size)
{
    const float* x    = (const float*)d_in[0];
    const void*  ei   = d_in[1];
    const float* w1a  = (const float*)d_in[2];
    const float* b1a  = (const float*)d_in[3];
    const float* w1b  = (const float*)d_in[4];
    const float* b1b  = (const float*)d_in[5];
    const float* eps1 = (const float*)d_in[6];
    const float* w2a  = (const float*)d_in[7];
    const float* b2a  = (const float*)d_in[8];
    const float* w2b  = (const float*)d_in[9];
    const float* b2b  = (const float*)d_in[10];
    const float* eps2 = (const float*)d_in[11];
    float* out = (float*)d_out;

    float *u1T, *h1T, *hrel, *u2T, *tT;
    int *deg;
    cudaGetSymbolAddress((void**)&u1T, g_u1T);
    cudaGetSymbolAddress((void**)&h1T, g_h1T);
    cudaGetSymbolAddress((void**)&hrel, g_hrel);
    cudaGetSymbolAddress((void**)&u2T, g_u2T);
    cudaGetSymbolAddress((void**)&tT, g_tT);
    cudaGetSymbolAddress((void**)&deg, g_deg);

    cudaFuncSetAttribute(k1a_kernel, cudaFuncAttributeMaxDynamicSharedMemorySize, SMEM_K1A);
    cudaFuncSetAttribute(k1b_kernel, cudaFuncAttributeMaxDynamicSharedMemorySize, SMEM_K1B);
    cudaFuncSetAttribute(k2a_kernel, cudaFuncAttributeMaxDynamicSharedMemorySize, SMEM_K1B);
    cudaFuncSetAttribute(k2b_kernel, cudaFuncAttributeMaxDynamicSharedMemorySize, SMEM_K2B);

    const int NB = (N_NODES + 63) / 64;   // 782

    detect_ei_kernel<<<1, 512>>>((const unsigned int*)ei);
    cudaMemsetAsync(deg, 0, N_NODES * sizeof(int));
    fill_kernel<<<N_EDGES / 256, 256>>>(ei);

    // layer 1
    agg1_kernel<<<NB, 256>>>(x, eps1, u1T);
    k1a_kernel<<<NB, 256, SMEM_K1A>>>(u1T, w1a, b1a, h1T);
    k1b_kernel<<<NB, 256, SMEM_K1B>>>(h1T, w1b, b1b, hrel);

    // layer 2
    agg2_kernel<<<NB, 256>>>(hrel, eps2, u2T);
    k2a_kernel<<<NB, 256, SMEM_K1B>>>(u2T, w2a, b2a, tT);
    k2b_kernel<<<NB, 256, SMEM_K2B>>>(tT, w2b, b2b, out);
}

// round 7
// speedup vs baseline: 1.0897x; 1.0897x over previous
#include <cuda_runtime.h>

#define N_NODES 50000
#define N_EDGES 800000
#define IN_C  64
#define HID_C 128
#define OUT_C 40
#define CAP   96      // neighbor bucket capacity (Poisson(16): P(deg>96) ~ 1e-40)

// ---------------- scratch (no allocations allowed) ----------------
__device__ float g_u1[N_NODES * IN_C];      // (1+eps1)*x + agg1
__device__ float g_hrel[N_NODES * HID_C];   // relu(gin1 output)
__device__ float g_u2[N_NODES * HID_C];     // (1+eps2)*hrel + agg2
__device__ int   g_deg[N_NODES];
__device__ int   g_bucket[N_NODES * CAP];   // 19.2 MB
__device__ int   g_ei_is64;

// ---------------- dtype detection (parallel) ----------------
__global__ void detect_ei_kernel(const unsigned int* __restrict__ w) {
    int ok = (w[2 * threadIdx.x + 1] == 0u) ? 1 : 0;
    int all = __syncthreads_and(ok);
    if (threadIdx.x == 0) g_ei_is64 = all;
}

// ---------------- bucket fill ----------------
__global__ void __launch_bounds__(256) fill_kernel(const void* __restrict__ eiv) {
    int e = blockIdx.x * 256 + threadIdx.x;   // exactly N_EDGES threads
    int s, d;
    if (g_ei_is64) {
        const long long* ei = (const long long*)eiv;
        s = (int)ei[e];
        d = (int)ei[N_EDGES + e];
    } else {
        const int* ei = (const int*)eiv;
        s = ei[e];
        d = ei[N_EDGES + e];
    }
    if ((unsigned)s >= N_NODES || (unsigned)d >= N_NODES) return;
    int pos = atomicAdd(&g_deg[d], 1);
    if (pos < CAP) g_bucket[d * CAP + pos] = s;
}

// ---------------- gather-aggregate layer 1 ----------------
__global__ void __launch_bounds__(256) agg1_kernel(
    const float* __restrict__ x, const float* __restrict__ eps1p,
    float* __restrict__ u1)
{
    int n = blockIdx.x * 8 + (threadIdx.x >> 5);   // 6250 blocks * 8 warps
    int lane = threadIdx.x & 31;
    int deg = g_deg[n];
    if (deg > CAP) deg = CAP;
    const int* bkt = &g_bucket[n * CAP];
    float2 acc = make_float2(0.f, 0.f);
    for (int i = 0; i < deg; i++) {
        int s = bkt[i];
        float2 v = *reinterpret_cast<const float2*>(x + (size_t)s * IN_C + lane * 2);
        acc.x += v.x; acc.y += v.y;
    }
    float ep = 1.0f + *eps1p;
    float2 xv = *reinterpret_cast<const float2*>(x + (size_t)n * IN_C + lane * 2);
    float2 o = make_float2(ep * xv.x + acc.x, ep * xv.y + acc.y);
    *reinterpret_cast<float2*>(u1 + (size_t)n * IN_C + lane * 2) = o;
}

// ---------------- gather-aggregate layer 2 ----------------
__global__ void __launch_bounds__(256) agg2_kernel(
    const float* __restrict__ h, const float* __restrict__ eps2p,
    float* __restrict__ u2)
{
    int n = blockIdx.x * 8 + (threadIdx.x >> 5);
    int lane = threadIdx.x & 31;
    int deg = g_deg[n];
    if (deg > CAP) deg = CAP;
    const int* bkt = &g_bucket[n * CAP];
    float4 acc = make_float4(0.f, 0.f, 0.f, 0.f);
    for (int i = 0; i < deg; i++) {
        int s = bkt[i];
        float4 v = *reinterpret_cast<const float4*>(h + (size_t)s * HID_C + lane * 4);
        acc.x += v.x; acc.y += v.y; acc.z += v.z; acc.w += v.w;
    }
    float ep = 1.0f + *eps2p;
    float4 hv = *reinterpret_cast<const float4*>(h + (size_t)n * HID_C + lane * 4);
    float4 o = make_float4(ep * hv.x + acc.x, ep * hv.y + acc.y,
                           ep * hv.z + acc.z, ep * hv.w + acc.w);
    *reinterpret_cast<float4*>(u2 + (size_t)n * HID_C + lane * 4) = o;
}

// ================= MLP layer 1 =================
// 1024 threads, 128 nodes / block, 4 nodes per warp (32 warps -> occ ~49%)
#define A_W1AT 0          // [128][68]
#define A_W1BT 8704       // [128][132]
#define A_B1A  25600
#define A_B1B  25728
#define A_XIN  25856      // [128][68]
#define A_HID  34560      // [128][132]
#define SMEM_A_BYTES (51456 * 4)

__global__ void __launch_bounds__(1024, 1) mlp1_kernel(
    const float* __restrict__ u1,
    const float* __restrict__ w1a, const float* __restrict__ b1a,
    const float* __restrict__ w1b, const float* __restrict__ b1b,
    float* __restrict__ hrel)
{
    extern __shared__ float sm[];
    float* w1aT = sm + A_W1AT;
    float* w1bT = sm + A_W1BT;
    float* b1as = sm + A_B1A;
    float* b1bs = sm + A_B1B;
    float* xin  = sm + A_XIN;
    float* hid  = sm + A_HID;

    const int tid = threadIdx.x;
    const int n0 = blockIdx.x * 128;

    for (int i = tid; i < IN_C * HID_C; i += 1024) {
        int c = i >> 7, j = i & 127;
        w1aT[j * 68 + c] = w1a[i];
    }
    for (int i = tid; i < HID_C * HID_C; i += 1024) {
        int c = i >> 7, j = i & 127;
        w1bT[j * 132 + c] = w1b[i];
    }
    if (tid < 128) { b1as[tid] = b1a[tid]; b1bs[tid] = b1b[tid]; }

    for (int i = tid; i < 128 * IN_C; i += 1024) {
        int n = i >> 6, c = i & 63;
        int g = n0 + n;
        xin[n * 68 + c] = (g < N_NODES) ? u1[(size_t)g * IN_C + c] : 0.0f;
    }
    __syncthreads();

    const int tx = tid & 31;
    const int ty = tid >> 5;     // 32 warps, 4 nodes each

    // ---- GEMV 1: 64 -> 128, relu ----
    {
        float acc[4][4];
        #pragma unroll
        for (int nn = 0; nn < 4; nn++)
            #pragma unroll
            for (int jj = 0; jj < 4; jj++)
                acc[nn][jj] = b1as[tx + 32 * jj];

        for (int c = 0; c < IN_C; c += 4) {
            float4 wv[4];
            #pragma unroll
            for (int jj = 0; jj < 4; jj++)
                wv[jj] = *reinterpret_cast<const float4*>(&w1aT[(tx + 32 * jj) * 68 + c]);
            #pragma unroll
            for (int nn = 0; nn < 4; nn++) {
                float4 xv = *reinterpret_cast<const float4*>(&xin[(ty * 4 + nn) * 68 + c]);
                #pragma unroll
                for (int jj = 0; jj < 4; jj++) {
                    acc[nn][jj] += xv.x * wv[jj].x;
                    acc[nn][jj] += xv.y * wv[jj].y;
                    acc[nn][jj] += xv.z * wv[jj].z;
                    acc[nn][jj] += xv.w * wv[jj].w;
                }
            }
        }
        #pragma unroll
        for (int nn = 0; nn < 4; nn++)
            #pragma unroll
            for (int jj = 0; jj < 4; jj++)
                hid[(ty * 4 + nn) * 132 + tx + 32 * jj] = fmaxf(acc[nn][jj], 0.0f);
    }
    __syncwarp();   // hid rows of node group ty are warp-private

    // ---- GEMV 2: 128 -> 128, relu, store ----
    {
        float acc[4][4];
        #pragma unroll
        for (int nn = 0; nn < 4; nn++)
            #pragma unroll
            for (int jj = 0; jj < 4; jj++)
                acc[nn][jj] = b1bs[tx + 32 * jj];

        for (int c = 0; c < HID_C; c += 4) {
            float4 wv[4];
            #pragma unroll
            for (int jj = 0; jj < 4; jj++)
                wv[jj] = *reinterpret_cast<const float4*>(&w1bT[(tx + 32 * jj) * 132 + c]);
            #pragma unroll
            for (int nn = 0; nn < 4; nn++) {
                float4 xv = *reinterpret_cast<const float4*>(&hid[(ty * 4 + nn) * 132 + c]);
                #pragma unroll
                for (int jj = 0; jj < 4; jj++) {
                    acc[nn][jj] += xv.x * wv[jj].x;
                    acc[nn][jj] += xv.y * wv[jj].y;
                    acc[nn][jj] += xv.z * wv[jj].z;
                    acc[nn][jj] += xv.w * wv[jj].w;
                }
            }
        }
        #pragma unroll
        for (int nn = 0; nn < 4; nn++) {
            int g = n0 + ty * 4 + nn;
            if (g < N_NODES) {
                #pragma unroll
                for (int jj = 0; jj < 4; jj++)
                    hrel[(size_t)g * HID_C + tx + 32 * jj] = fmaxf(acc[nn][jj], 0.0f);
            }
        }
    }
}

// ================= MLP layer 2 + log_softmax =================
// 1024 threads, 128 nodes / block, 4 nodes per warp. uin reused as tmid.
#define B_W2AT 0          // [128][132]
#define B_W2BT 16896      // [40][132]
#define B_B2A  22176
#define B_B2B  22304
#define B_UIN  22368      // [128][132]  (also tmid)
#define B_OOUT 39264      // [128][40]
#define B_CORR 44384
#define SMEM_B_BYTES (44512 * 4)

__global__ void __launch_bounds__(1024, 1) mlp2_kernel(
    const float* __restrict__ u2,
    const float* __restrict__ w2a, const float* __restrict__ b2a,
    const float* __restrict__ w2b, const float* __restrict__ b2b,
    float* __restrict__ out)
{
    extern __shared__ float sm[];
    float* w2aT = sm + B_W2AT;
    float* w2bT = sm + B_W2BT;
    float* b2as = sm + B_B2A;
    float* b2bs = sm + B_B2B;
    float* uin  = sm + B_UIN;
    float* oout = sm + B_OOUT;
    float* corr = sm + B_CORR;

    const int tid = threadIdx.x;
    const int n0 = blockIdx.x * 128;

    for (int i = tid; i < HID_C * HID_C; i += 1024) {
        int c = i >> 7, j = i & 127;
        w2aT[j * 132 + c] = w2a[i];
    }
    for (int i = tid; i < HID_C * OUT_C; i += 1024) {
        int c = i / OUT_C, j = i - c * OUT_C;
        w2bT[j * 132 + c] = w2b[i];
    }
    if (tid < 128) b2as[tid] = b2a[tid];
    if (tid < OUT_C) b2bs[tid] = b2b[tid];

    for (int i = tid; i < 128 * HID_C; i += 1024) {
        int n = i >> 7, c = i & 127;
        int g = n0 + n;
        uin[n * 132 + c] = (g < N_NODES) ? u2[(size_t)g * HID_C + c] : 0.0f;
    }
    __syncthreads();

    const int tx = tid & 31;
    const int ty = tid >> 5;

    // ---- GEMV 2a: 128 -> 128, relu; write back into uin (warp-private rows) ----
    {
        float acc[4][4];
        #pragma unroll
        for (int nn = 0; nn < 4; nn++)
            #pragma unroll
            for (int jj = 0; jj < 4; jj++)
                acc[nn][jj] = b2as[tx + 32 * jj];

        for (int c = 0; c < HID_C; c += 4) {
            float4 wv[4];
            #pragma unroll
            for (int jj = 0; jj < 4; jj++)
                wv[jj] = *reinterpret_cast<const float4*>(&w2aT[(tx + 32 * jj) * 132 + c]);
            #pragma unroll
            for (int nn = 0; nn < 4; nn++) {
                float4 xv = *reinterpret_cast<const float4*>(&uin[(ty * 4 + nn) * 132 + c]);
                #pragma unroll
                for (int jj = 0; jj < 4; jj++) {
                    acc[nn][jj] += xv.x * wv[jj].x;
                    acc[nn][jj] += xv.y * wv[jj].y;
                    acc[nn][jj] += xv.z * wv[jj].z;
                    acc[nn][jj] += xv.w * wv[jj].w;
                }
            }
        }
        #pragma unroll
        for (int nn = 0; nn < 4; nn++)
            #pragma unroll
            for (int jj = 0; jj < 4; jj++)
                uin[(ty * 4 + nn) * 132 + tx + 32 * jj] = fmaxf(acc[nn][jj], 0.0f);
    }
    __syncthreads();

    // ---- GEMV 2b: 128 -> 40 ----
    for (int idx = tid; idx < 128 * OUT_C; idx += 1024) {
        int n = idx / OUT_C;
        int j = idx - n * OUT_C;
        float a = b2bs[j];
        const float* wr = &w2bT[j * 132];
        const float* tr = &uin[n * 132];
        #pragma unroll
        for (int c = 0; c < HID_C; c += 4) {
            float4 wv = *reinterpret_cast<const float4*>(wr + c);
            float4 tv = *reinterpret_cast<const float4*>(tr + c);
            a += wv.x * tv.x + wv.y * tv.y + wv.z * tv.z + wv.w * tv.w;
        }
        oout[idx] = a;
    }
    __syncthreads();

    // ---- log_softmax ----
    if (tid < 128) {
        const float* o = &oout[tid * OUT_C];
        float m = o[0];
        #pragma unroll
        for (int j = 1; j < OUT_C; j++) m = fmaxf(m, o[j]);
        float s = 0.0f;
        #pragma unroll
        for (int j = 0; j < OUT_C; j++) s += __expf(o[j] - m);
        corr[tid] = m + logf(s);
    }
    __syncthreads();

    for (int idx = tid; idx < 128 * OUT_C; idx += 1024) {
        int n = idx / OUT_C;
        int g = n0 + n;
        if (g < N_NODES) out[(size_t)g * OUT_C + (idx - n * OUT_C)] = oout[idx] - corr[n];
    }
}

// ================= launch =================
extern "C" void kernel_launch(void* const* d_in, const int* in_sizes, int n_in,
                              void* d_out, int out_size)
{
    const float* x    = (const float*)d_in[0];
    const void*  ei   = d_in[1];
    const float* w1a  = (const float*)d_in[2];
    const float* b1a  = (const float*)d_in[3];
    const float* w1b  = (const float*)d_in[4];
    const float* b1b  = (const float*)d_in[5];
    const float* eps1 = (const float*)d_in[6];
    const float* w2a  = (const float*)d_in[7];
    const float* b2a  = (const float*)d_in[8];
    const float* w2b  = (const float*)d_in[9];
    const float* b2b  = (const float*)d_in[10];
    const float* eps2 = (const float*)d_in[11];
    float* out = (float*)d_out;

    float *u1, *hrel, *u2;
    int *deg;
    cudaGetSymbolAddress((void**)&u1, g_u1);
    cudaGetSymbolAddress((void**)&hrel, g_hrel);
    cudaGetSymbolAddress((void**)&u2, g_u2);
    cudaGetSymbolAddress((void**)&deg, g_deg);

    cudaFuncSetAttribute(mlp1_kernel, cudaFuncAttributeMaxDynamicSharedMemorySize, SMEM_A_BYTES);
    cudaFuncSetAttribute(mlp2_kernel, cudaFuncAttributeMaxDynamicSharedMemorySize, SMEM_B_BYTES);

    detect_ei_kernel<<<1, 512>>>((const unsigned int*)ei);
    cudaMemsetAsync(deg, 0, N_NODES * sizeof(int));
    fill_kernel<<<N_EDGES / 256, 256>>>(ei);

    // layer 1
    agg1_kernel<<<N_NODES / 8, 256>>>(x, eps1, u1);
    mlp1_kernel<<<(N_NODES + 127) / 128, 1024, SMEM_A_BYTES>>>(
        u1, w1a, b1a, w1b, b1b, hrel);

    // layer 2
    agg2_kernel<<<N_NODES / 8, 256>>>(hrel, eps2, u2);
    mlp2_kernel<<<(N_NODES + 127) / 128, 1024, SMEM_B_BYTES>>>(
        u2, w2a, b2a, w2b, b2b, out);
}

// round 10
// speedup vs baseline: 1.1633x; 1.0675x over previous
#include <cuda_runtime.h>

#define N_NODES 50000
#define N_EDGES 800000
#define IN_C  64
#define HID_C 128
#define OUT_C 40
#define CAP   96      // neighbor bucket capacity (Poisson(16): P(deg>96) ~ 1e-40)

// ---------------- scratch (no allocations allowed) ----------------
__device__ float g_u1[N_NODES * IN_C];      // (1+eps1)*x + agg1
__device__ float g_hrel[N_NODES * HID_C];   // relu(gin1 output)
__device__ float g_u2[N_NODES * HID_C];     // (1+eps2)*hrel + agg2
__device__ int   g_deg[N_NODES];
__device__ int   g_bucket[N_NODES * CAP];   // 19.2 MB
__device__ int   g_ei_is64;

// ---------------- packed f32x2 helpers (K-dim packing: no movs) ----------
typedef unsigned long long ull;
__device__ __forceinline__ ull fma2(ull a, ull b, ull c) {
    ull d;
    asm("fma.rn.f32x2 %0, %1, %2, %3;" : "=l"(d) : "l"(a), "l"(b), "l"(c));
    return d;
}
__device__ __forceinline__ float unpack_sum(ull v) {
    float lo, hi;
    asm("mov.b64 {%0, %1}, %2;" : "=f"(lo), "=f"(hi) : "l"(v));
    return lo + hi;
}
union F4U2 { float4 f; ull u[2]; };

// ---------------- dtype detection (parallel) ----------------
__global__ void detect_ei_kernel(const unsigned int* __restrict__ w) {
    int ok = (w[2 * threadIdx.x + 1] == 0u) ? 1 : 0;
    int all = __syncthreads_and(ok);
    if (threadIdx.x == 0) g_ei_is64 = all;
}

// ---------------- bucket fill ----------------
__global__ void __launch_bounds__(256) fill_kernel(const void* __restrict__ eiv) {
    int e = blockIdx.x * 256 + threadIdx.x;   // exactly N_EDGES threads
    int s, d;
    if (g_ei_is64) {
        const long long* ei = (const long long*)eiv;
        s = (int)ei[e];
        d = (int)ei[N_EDGES + e];
    } else {
        const int* ei = (const int*)eiv;
        s = ei[e];
        d = ei[N_EDGES + e];
    }
    if ((unsigned)s >= N_NODES || (unsigned)d >= N_NODES) return;
    int pos = atomicAdd(&g_deg[d], 1);
    if (pos < CAP) g_bucket[d * CAP + pos] = s;
}

// ---------------- gather-aggregate layer 1 ----------------
__global__ void __launch_bounds__(256) agg1_kernel(
    const float* __restrict__ x, const float* __restrict__ eps1p,
    float* __restrict__ u1)
{
    int n = blockIdx.x * 8 + (threadIdx.x >> 5);   // 6250 blocks * 8 warps
    int lane = threadIdx.x & 31;
    int deg = g_deg[n];
    if (deg > CAP) deg = CAP;
    const int* bkt = &g_bucket[n * CAP];
    float2 acc = make_float2(0.f, 0.f);
    for (int i = 0; i < deg; i++) {
        int s = bkt[i];
        float2 v = *reinterpret_cast<const float2*>(x + (size_t)s * IN_C + lane * 2);
        acc.x += v.x; acc.y += v.y;
    }
    float ep = 1.0f + *eps1p;
    float2 xv = *reinterpret_cast<const float2*>(x + (size_t)n * IN_C + lane * 2);
    float2 o = make_float2(ep * xv.x + acc.x, ep * xv.y + acc.y);
    *reinterpret_cast<float2*>(u1 + (size_t)n * IN_C + lane * 2) = o;
}

// ---------------- gather-aggregate layer 2 ----------------
__global__ void __launch_bounds__(256) agg2_kernel(
    const float* __restrict__ h, const float* __restrict__ eps2p,
    float* __restrict__ u2)
{
    int n = blockIdx.x * 8 + (threadIdx.x >> 5);
    int lane = threadIdx.x & 31;
    int deg = g_deg[n];
    if (deg > CAP) deg = CAP;
    const int* bkt = &g_bucket[n * CAP];
    float4 acc = make_float4(0.f, 0.f, 0.f, 0.f);
    for (int i = 0; i < deg; i++) {
        int s = bkt[i];
        float4 v = *reinterpret_cast<const float4*>(h + (size_t)s * HID_C + lane * 4);
        acc.x += v.x; acc.y += v.y; acc.z += v.z; acc.w += v.w;
    }
    float ep = 1.0f + *eps2p;
    float4 hv = *reinterpret_cast<const float4*>(h + (size_t)n * HID_C + lane * 4);
    float4 o = make_float4(ep * hv.x + acc.x, ep * hv.y + acc.y,
                           ep * hv.z + acc.z, ep * hv.w + acc.w);
    *reinterpret_cast<float4*>(u2 + (size_t)n * HID_C + lane * 4) = o;
}

// ================= MLP layer 1 =================
// 512 threads, 128 nodes / block, 8 nodes per warp; K-packed f32x2 math.
#define A_W1AT 0          // [128][68]
#define A_W1BT 8704       // [128][132]
#define A_B1A  25600
#define A_B1B  25728
#define A_XIN  25856      // [128][68]
#define A_HID  34560      // [128][132]
#define SMEM_A_BYTES (51456 * 4)

__global__ void __launch_bounds__(512, 1) mlp1_kernel(
    const float* __restrict__ u1,
    const float* __restrict__ w1a, const float* __restrict__ b1a,
    const float* __restrict__ w1b, const float* __restrict__ b1b,
    float* __restrict__ hrel)
{
    extern __shared__ float sm[];
    float* w1aT = sm + A_W1AT;
    float* w1bT = sm + A_W1BT;
    float* b1as = sm + A_B1A;
    float* b1bs = sm + A_B1B;
    float* xin  = sm + A_XIN;
    float* hid  = sm + A_HID;

    const int tid = threadIdx.x;
    const int n0 = blockIdx.x * 128;

    for (int i = tid; i < IN_C * HID_C; i += 512) {
        int c = i >> 7, j = i & 127;
        w1aT[j * 68 + c] = w1a[i];
    }
    for (int i = tid; i < HID_C * HID_C; i += 512) {
        int c = i >> 7, j = i & 127;
        w1bT[j * 132 + c] = w1b[i];
    }
    if (tid < 128) { b1as[tid] = b1a[tid]; b1bs[tid] = b1b[tid]; }

    for (int i = tid; i < 128 * IN_C; i += 512) {
        int n = i >> 6, c = i & 63;
        int g = n0 + n;
        xin[n * 68 + c] = (g < N_NODES) ? u1[(size_t)g * IN_C + c] : 0.0f;
    }
    __syncthreads();

    const int tx = tid & 31;
    const int ty = tid >> 5;     // 16 warps, 8 nodes each

    // ---- GEMV 1: 64 -> 128, relu (f32x2 over K-pairs) ----
    {
        ull acc[8][4];
        #pragma unroll
        for (int nn = 0; nn < 8; nn++)
            #pragma unroll
            for (int jj = 0; jj < 4; jj++)
                acc[nn][jj] = 0ULL;

        for (int c = 0; c < IN_C; c += 4) {
            F4U2 wv[4];
            #pragma unroll
            for (int jj = 0; jj < 4; jj++)
                wv[jj].f = *reinterpret_cast<const float4*>(&w1aT[(tx + 32 * jj) * 68 + c]);
            #pragma unroll
            for (int nn = 0; nn < 8; nn++) {
                F4U2 xv;
                xv.f = *reinterpret_cast<const float4*>(&xin[(ty * 8 + nn) * 68 + c]);
                #pragma unroll
                for (int jj = 0; jj < 4; jj++) {
                    acc[nn][jj] = fma2(xv.u[0], wv[jj].u[0], acc[nn][jj]);
                    acc[nn][jj] = fma2(xv.u[1], wv[jj].u[1], acc[nn][jj]);
                }
            }
        }
        #pragma unroll
        for (int nn = 0; nn < 8; nn++)
            #pragma unroll
            for (int jj = 0; jj < 4; jj++)
                hid[(ty * 8 + nn) * 132 + tx + 32 * jj] =
                    fmaxf(unpack_sum(acc[nn][jj]) + b1as[tx + 32 * jj], 0.0f);
    }
    __syncwarp();   // hid rows of node group ty are warp-private

    // ---- GEMV 2: 128 -> 128, relu, store ----
    {
        ull acc[8][4];
        #pragma unroll
        for (int nn = 0; nn < 8; nn++)
            #pragma unroll
            for (int jj = 0; jj < 4; jj++)
                acc[nn][jj] = 0ULL;

        for (int c = 0; c < HID_C; c += 4) {
            F4U2 wv[4];
            #pragma unroll
            for (int jj = 0; jj < 4; jj++)
                wv[jj].f = *reinterpret_cast<const float4*>(&w1bT[(tx + 32 * jj) * 132 + c]);
            #pragma unroll
            for (int nn = 0; nn < 8; nn++) {
                F4U2 xv;
                xv.f = *reinterpret_cast<const float4*>(&hid[(ty * 8 + nn) * 132 + c]);
                #pragma unroll
                for (int jj = 0; jj < 4; jj++) {
                    acc[nn][jj] = fma2(xv.u[0], wv[jj].u[0], acc[nn][jj]);
                    acc[nn][jj] = fma2(xv.u[1], wv[jj].u[1], acc[nn][jj]);
                }
            }
        }
        #pragma unroll
        for (int nn = 0; nn < 8; nn++) {
            int g = n0 + ty * 8 + nn;
            if (g < N_NODES) {
                #pragma unroll
                for (int jj = 0; jj < 4; jj++)
                    hrel[(size_t)g * HID_C + tx + 32 * jj] =
                        fmaxf(unpack_sum(acc[nn][jj]) + b1bs[tx + 32 * jj], 0.0f);
            }
        }
    }
}

// ================= MLP layer 2 + log_softmax =================
// 512 threads, 128 nodes / block. uin reused as tmid (warp-private rows).
#define B_W2AT 0          // [128][132]
#define B_W2BT 16896      // [40][132]
#define B_B2A  22176
#define B_B2B  22304
#define B_UIN  22368      // [128][132]  (also tmid)
#define B_OOUT 39264      // [128][40]
#define B_CORR 44384
#define SMEM_B_BYTES (44512 * 4)

__global__ void __launch_bounds__(512, 1) mlp2_kernel(
    const float* __restrict__ u2,
    const float* __restrict__ w2a, const float* __restrict__ b2a,
    const float* __restrict__ w2b, const float* __restrict__ b2b,
    float* __restrict__ out)
{
    extern __shared__ float sm[];
    float* w2aT = sm + B_W2AT;
    float* w2bT = sm + B_W2BT;
    float* b2as = sm + B_B2A;
    float* b2bs = sm + B_B2B;
    float* uin  = sm + B_UIN;
    float* oout = sm + B_OOUT;
    float* corr = sm + B_CORR;

    const int tid = threadIdx.x;
    const int n0 = blockIdx.x * 128;

    for (int i = tid; i < HID_C * HID_C; i += 512) {
        int c = i >> 7, j = i & 127;
        w2aT[j * 132 + c] = w2a[i];
    }
    for (int i = tid; i < HID_C * OUT_C; i += 512) {
        int c = i / OUT_C, j = i - c * OUT_C;
        w2bT[j * 132 + c] = w2b[i];
    }
    if (tid < 128) b2as[tid] = b2a[tid];
    if (tid < OUT_C) b2bs[tid] = b2b[tid];

    for (int i = tid; i < 128 * HID_C; i += 512) {
        int n = i >> 7, c = i & 127;
        int g = n0 + n;
        uin[n * 132 + c] = (g < N_NODES) ? u2[(size_t)g * HID_C + c] : 0.0f;
    }
    __syncthreads();

    const int tx = tid & 31;
    const int ty = tid >> 5;

    // ---- GEMV 2a: 128 -> 128, relu; write back into uin (warp-private) ----
    {
        ull acc[8][4];
        #pragma unroll
        for (int nn = 0; nn < 8; nn++)
            #pragma unroll
            for (int jj = 0; jj < 4; jj++)
                acc[nn][jj] = 0ULL;

        for (int c = 0; c < HID_C; c += 4) {
            F4U2 wv[4];
            #pragma unroll
            for (int jj = 0; jj < 4; jj++)
                wv[jj].f = *reinterpret_cast<const float4*>(&w2aT[(tx + 32 * jj) * 132 + c]);
            #pragma unroll
            for (int nn = 0; nn < 8; nn++) {
                F4U2 xv;
                xv.f = *reinterpret_cast<const float4*>(&uin[(ty * 8 + nn) * 132 + c]);
                #pragma unroll
                for (int jj = 0; jj < 4; jj++) {
                    acc[nn][jj] = fma2(xv.u[0], wv[jj].u[0], acc[nn][jj]);
                    acc[nn][jj] = fma2(xv.u[1], wv[jj].u[1], acc[nn][jj]);
                }
            }
        }
        #pragma unroll
        for (int nn = 0; nn < 8; nn++)
            #pragma unroll
            for (int jj = 0; jj < 4; jj++)
                uin[(ty * 8 + nn) * 132 + tx + 32 * jj] =
                    fmaxf(unpack_sum(acc[nn][jj]) + b2as[tx + 32 * jj], 0.0f);
    }
    __syncthreads();

    // ---- GEMV 2b: 128 -> 40 (f32x2 over K) ----
    for (int idx = tid; idx < 128 * OUT_C; idx += 512) {
        int n = idx / OUT_C;
        int j = idx - n * OUT_C;
        ull a = 0ULL;
        const float* wr = &w2bT[j * 132];
        const float* tr = &uin[n * 132];
        #pragma unroll
        for (int c = 0; c < HID_C; c += 4) {
            F4U2 wv, tv;
            wv.f = *reinterpret_cast<const float4*>(wr + c);
            tv.f = *reinterpret_cast<const float4*>(tr + c);
            a = fma2(tv.u[0], wv.u[0], a);
            a = fma2(tv.u[1], wv.u[1], a);
        }
        oout[idx] = unpack_sum(a) + b2bs[j];
    }
    __syncthreads();

    // ---- log_softmax ----
    if (tid < 128) {
        const float* o = &oout[tid * OUT_C];
        float m = o[0];
        #pragma unroll
        for (int j = 1; j < OUT_C; j++) m = fmaxf(m, o[j]);
        float s = 0.0f;
        #pragma unroll
        for (int j = 0; j < OUT_C; j++) s += __expf(o[j] - m);
        corr[tid] = m + logf(s);
    }
    __syncthreads();

    for (int idx = tid; idx < 128 * OUT_C; idx += 512) {
        int n = idx / OUT_C;
        int g = n0 + n;
        if (g < N_NODES) out[(size_t)g * OUT_C + (idx - n * OUT_C)] = oout[idx] - corr[n];
    }
}

// ================= launch =================
extern "C" void kernel_launch(void* const* d_in, const int* in_sizes, int n_in,
                              void* d_out, int out_size)
{
    const float* x    = (const float*)d_in[0];
    const void*  ei   = d_in[1];
    const float* w1a  = (const float*)d_in[2];
    const float* b1a  = (const float*)d_in[3];
    const float* w1b  = (const float*)d_in[4];
    const float* b1b  = (const float*)d_in[5];
    const float* eps1 = (const float*)d_in[6];
    const float* w2a  = (const float*)d_in[7];
    const float* b2a  = (const float*)d_in[8];
    const float* w2b  = (const float*)d_in[9];
    const float* b2b  = (const float*)d_in[10];
    const float* eps2 = (const float*)d_in[11];
    float* out = (float*)d_out;

    float *u1, *hrel, *u2;
    int *deg;
    cudaGetSymbolAddress((void**)&u1, g_u1);
    cudaGetSymbolAddress((void**)&hrel, g_hrel);
    cudaGetSymbolAddress((void**)&u2, g_u2);
    cudaGetSymbolAddress((void**)&deg, g_deg);

    cudaFuncSetAttribute(mlp1_kernel, cudaFuncAttributeMaxDynamicSharedMemorySize, SMEM_A_BYTES);
    cudaFuncSetAttribute(mlp2_kernel, cudaFuncAttributeMaxDynamicSharedMemorySize, SMEM_B_BYTES);

    detect_ei_kernel<<<1, 512>>>((const unsigned int*)ei);
    cudaMemsetAsync(deg, 0, N_NODES * sizeof(int));
    fill_kernel<<<N_EDGES / 256, 256>>>(ei);

    // layer 1
    agg1_kernel<<<N_NODES / 8, 256>>>(x, eps1, u1);
    mlp1_kernel<<<(N_NODES + 127) / 128, 512, SMEM_A_BYTES>>>(
        u1, w1a, b1a, w1b, b1b, hrel);

    // layer 2
    agg2_kernel<<<N_NODES / 8, 256>>>(hrel, eps2, u2);
    mlp2_kernel<<<(N_NODES + 127) / 128, 512, SMEM_B_BYTES>>>(
        u2, w2a, b2a, w2b, b2b, out);
}